// round 15
// baseline (speedup 1.0000x reference)
#include <cuda_runtime.h>
#include <cuda_fp16.h>
#include <cstdint>

typedef unsigned int u32;

#define N_HEADS 16
#define NPG   64
#define IN_F  128
#define OUT_F 128

// Pre-built fp16 swizzled W images, exactly the main kernel's Wk smem layout:
// per head: [128 k][64 u32 words]; 16B chunk c of row k stored at chunk (c ^ (k&7)).
__device__ u32 g_wimg[N_HEADS * IN_F * 64];    // 512 KB

#define WK_WORDS (IN_F * 64)   // 8192 u32 = 32 KB
#define XT_WORDS (NPG * 64)    // 4096 u32 = 16 KB
#define SMEM_BYTES ((WK_WORDS + XT_WORDS) * 4)   // 49152

__device__ __forceinline__ u32 pack_h2(float lo, float hi) {
    __half2 h = __floats2half2_rn(lo, hi);
    return *(u32*)&h;
}
__device__ __forceinline__ u32 smem_addr(const void* p) {
    return (u32)__cvta_generic_to_shared(p);
}

#define CP_ASYNC16(dst, src) \
    asm volatile("cp.async.cg.shared.global [%0], [%1], 16;" :: "r"(dst), "l"(src))
#define CP_COMMIT() asm volatile("cp.async.commit_group;" ::: "memory")
#define CP_WAIT0()  asm volatile("cp.async.wait_group 0;" ::: "memory")

#define LDSM_X4(r0, r1, r2, r3, a) \
    asm volatile("ldmatrix.sync.aligned.m8n8.x4.shared.b16 {%0,%1,%2,%3}, [%4];" \
        : "=r"(r0), "=r"(r1), "=r"(r2), "=r"(r3) : "r"(a))
#define LDSM_X4_T(r0, r1, r2, r3, a) \
    asm volatile("ldmatrix.sync.aligned.m8n8.x4.trans.shared.b16 {%0,%1,%2,%3}, [%4];" \
        : "=r"(r0), "=r"(r1), "=r"(r2), "=r"(r3) : "r"(a))

__device__ __forceinline__ void mma_f16(float* c, u32 a0, u32 a1, u32 a2, u32 a3,
                                        u32 b0, u32 b1)
{
    asm volatile(
        "mma.sync.aligned.m16n8k16.row.col.f32.f16.f16.f32 "
        "{%0,%1,%2,%3}, {%4,%5,%6,%7}, {%8,%9}, {%0,%1,%2,%3};"
        : "+f"(c[0]), "+f"(c[1]), "+f"(c[2]), "+f"(c[3])
        : "r"(a0), "r"(a1), "r"(a2), "r"(a3), "r"(b0), "r"(b1));
}

// ---------------- prep: W[h][k][n] fp32 -> fp16 swizzled image ----------------
__global__ void __launch_bounds__(256)
prep_kernel(const float* __restrict__ kern)
{
    const int h  = blockIdx.x >> 3;
    const int bk = blockIdx.x & 7;        // 16-k-row block
    const int tid = threadIdx.x;          // 256 tasks: 16 rows x 16 chunks
    const int kl  = tid >> 4;
    const int nc  = tid & 15;
    const int k   = bk * 16 + kl;

    const float4* src = (const float4*)(kern + ((size_t)h * IN_F + k) * OUT_F + nc * 8);
    float4 v0 = src[0], v1 = src[1];
    uint4 o;
    o.x = pack_h2(v0.x, v0.y);
    o.y = pack_h2(v0.z, v0.w);
    o.z = pack_h2(v1.x, v1.y);
    o.w = pack_h2(v1.z, v1.w);
    *(uint4*)&g_wimg[(size_t)h * WK_WORDS + k * 64 + ((nc ^ (k & 7)) << 2)] = o;
}

// ---------------- main ----------------
__global__ void __launch_bounds__(256, 2)
mhl_mma_kernel(const float* __restrict__ x,
               const int*   __restrict__ head,
               const float* __restrict__ bias,
               float*       __restrict__ out)
{
    extern __shared__ u32 smem[];
    u32* Wk = smem;               // [128 k][64 words], swizzled chunks (copied verbatim)
    u32* XT = smem + WK_WORDS;    // [64 node][64 words], swizzled chunks

    const int tid  = threadIdx.x;
    const int wid  = tid >> 5;             // 8 warps: 2m x 4n
    const int lane = tid & 31;
    const int gid  = lane >> 2;
    const int tig  = lane & 3;
    const int g    = blockIdx.x;
    const int h    = __ldg(head + g);

    const int m0 = (wid >> 2) * 32;        // 0, 32
    const int n0 = (wid & 3) * 32;         // 0, 32, 64, 96

    // ---- W: linear 32 KB cp.async copy of pre-swizzled image (L2-hot) ----
    {
        const u32* src = g_wimg + (size_t)h * WK_WORDS;
        const u32 dstb = smem_addr(Wk);
        #pragma unroll
        for (int i = 0; i < 8; i++) {
            const int idx = tid + i * 256;       // 2048 x 16B
            CP_ASYNC16(dstb + (u32)idx * 16u, src + idx * 4);
        }
        CP_COMMIT();
    }
    // ---- X: LDG.128 -> fp16 -> swizzled STS.128 (overlaps W cp.asyncs) ----
    {
        const float4* X4 = (const float4*)(x + (size_t)g * NPG * IN_F);
        #pragma unroll
        for (int it = 0; it < 4; it++) {
            const int idx  = tid + it * 256;     // 1024 chunks
            const int node = idx >> 4;
            const int kc   = idx & 15;
            float4 v0 = X4[node * 32 + kc * 2];
            float4 v1 = X4[node * 32 + kc * 2 + 1];
            uint4 o;
            o.x = pack_h2(v0.x, v0.y);
            o.y = pack_h2(v0.z, v0.w);
            o.z = pack_h2(v1.x, v1.y);
            o.w = pack_h2(v1.z, v1.w);
            *(uint4*)&XT[node * 64 + ((kc ^ (node & 7)) << 2)] = o;
        }
    }
    CP_WAIT0();
    __syncthreads();

    float acc[2][4][4];
    #pragma unroll
    for (int i = 0; i < 2; i++)
        #pragma unroll
        for (int j = 0; j < 4; j++)
            #pragma unroll
            for (int r = 0; r < 4; r++)
                acc[i][j][r] = 0.0f;

    // A (non-trans LDSM): rows = m, chunks along k
    const int arow0 = m0 + (lane & 7) + 8 * ((lane >> 3) & 1);
    const int akc   = (lane >> 4) & 1;
    const u32 abase0 = smem_addr(&XT[arow0 * 64]);
    const u32 abase1 = smem_addr(&XT[(arow0 + 16) * 64]);
    const int ae0 = arow0 & 7, ae1 = (arow0 + 16) & 7;

    // B (trans LDSM): rows = k, chunks along n
    const int brow_off = (lane & 7) + 8 * ((lane >> 3) & 1);
    const int bnc_off  = (lane >> 4) & 1;

    #pragma unroll
    for (int s = 0; s < 8; s++) {
        u32 a0[4], a1[4];
        LDSM_X4(a0[0], a0[1], a0[2], a0[3], abase0 + ((((2 * s) + akc) ^ ae0) << 4));
        LDSM_X4(a1[0], a1[1], a1[2], a1[3], abase1 + ((((2 * s) + akc) ^ ae1) << 4));
        const int krow = 16 * s + brow_off;
        const u32 bstride = smem_addr(&Wk[krow * 64]);
        u32 b[2][4];
        #pragma unroll
        for (int p = 0; p < 2; p++) {
            const int nc = (n0 >> 3) + 2 * p + bnc_off;
            LDSM_X4_T(b[p][0], b[p][1], b[p][2], b[p][3],
                      bstride + ((nc ^ (krow & 7)) << 4));
        }
        #pragma unroll
        for (int j = 0; j < 4; j++) {
            const int p = j >> 1, q = j & 1;
            mma_f16(acc[0][j], a0[0], a0[1], a0[2], a0[3], b[p][2 * q], b[p][2 * q + 1]);
            mma_f16(acc[1][j], a1[0], a1[1], a1[2], a1[3], b[p][2 * q], b[p][2 * q + 1]);
        }
    }

    // ---- epilogue: bias + coalesced float2 stores ----
    float bb[4][2];
    #pragma unroll
    for (int j = 0; j < 4; j++) {
        const int col = n0 + 8 * j + 2 * tig;
        bb[j][0] = __ldg(bias + (size_t)h * OUT_F + col);
        bb[j][1] = __ldg(bias + (size_t)h * OUT_F + col + 1);
    }

    #pragma unroll
    for (int i = 0; i < 2; i++) {
        const int node0 = g * NPG + m0 + 16 * i + gid;
        #pragma unroll
        for (int j = 0; j < 4; j++) {
            const int col = n0 + 8 * j + 2 * tig;
            float2 v0 = make_float2(acc[i][j][0] + bb[j][0], acc[i][j][1] + bb[j][1]);
            float2 v1 = make_float2(acc[i][j][2] + bb[j][0], acc[i][j][3] + bb[j][1]);
            *(float2*)&out[(size_t)node0 * OUT_F + col]       = v0;
            *(float2*)&out[(size_t)(node0 + 8) * OUT_F + col] = v1;
        }
    }
}

extern "C" void kernel_launch(void* const* d_in, const int* in_sizes, int n_in,
                              void* d_out, int out_size)
{
    const float* inputs = (const float*)d_in[0];
    const int*   head   = (const int*)d_in[2];
    const float* kern   = (const float*)d_in[3];
    const float* bias   = (const float*)d_in[4];
    float*       out    = (float*)d_out;
    const int n_graphs  = in_sizes[2];   // 256

    prep_kernel<<<N_HEADS * 8, 256>>>(kern);

    static bool attr_set = false;
    if (!attr_set) {
        cudaFuncSetAttribute(mhl_mma_kernel, cudaFuncAttributeMaxDynamicSharedMemorySize, SMEM_BYTES);
        attr_set = true;
    }
    mhl_mma_kernel<<<n_graphs, 256, SMEM_BYTES>>>(inputs, head, bias, out);
}

// round 16
// speedup vs baseline: 1.0269x; 1.0269x over previous
#include <cuda_runtime.h>
#include <cuda_fp16.h>
#include <cstdint>

typedef unsigned int u32;

#define NPG   64
#define IN_F  128
#define OUT_F 128

#define WK_WORDS (IN_F * 64)     // fp16 W image: 8192 u32 = 32 KB
#define XR_WORDS (NPG * IN_F)    // raw fp32 X:   8192 u32 = 32 KB
#define XT_WORDS (NPG * 64)      // fp16 X image: 4096 u32 = 16 KB
#define SMEM_BYTES ((WK_WORDS + XR_WORDS + XT_WORDS) * 4)   // 81920

__device__ __forceinline__ u32 pack_h2(float lo, float hi) {
    __half2 h = __floats2half2_rn(lo, hi);
    return *(u32*)&h;
}
__device__ __forceinline__ u32 smem_addr(const void* p) {
    return (u32)__cvta_generic_to_shared(p);
}

#define CP_ASYNC16(dst, src) \
    asm volatile("cp.async.cg.shared.global [%0], [%1], 16;" :: "r"(dst), "l"(src))
#define CP_COMMIT() asm volatile("cp.async.commit_group;" ::: "memory")
#define CP_WAIT0()  asm volatile("cp.async.wait_group 0;" ::: "memory")

#define LDSM_X4(r0, r1, r2, r3, a) \
    asm volatile("ldmatrix.sync.aligned.m8n8.x4.shared.b16 {%0,%1,%2,%3}, [%4];" \
        : "=r"(r0), "=r"(r1), "=r"(r2), "=r"(r3) : "r"(a))
#define LDSM_X4_T(r0, r1, r2, r3, a) \
    asm volatile("ldmatrix.sync.aligned.m8n8.x4.trans.shared.b16 {%0,%1,%2,%3}, [%4];" \
        : "=r"(r0), "=r"(r1), "=r"(r2), "=r"(r3) : "r"(a))

__device__ __forceinline__ void mma_f16(float* c, u32 a0, u32 a1, u32 a2, u32 a3,
                                        u32 b0, u32 b1)
{
    asm volatile(
        "mma.sync.aligned.m16n8k16.row.col.f32.f16.f16.f32 "
        "{%0,%1,%2,%3}, {%4,%5,%6,%7}, {%8,%9}, {%0,%1,%2,%3};"
        : "+f"(c[0]), "+f"(c[1]), "+f"(c[2]), "+f"(c[3])
        : "r"(a0), "r"(a1), "r"(a2), "r"(a3), "r"(b0), "r"(b1));
}

__global__ void __launch_bounds__(256, 2)
mhl_mma_kernel(const float* __restrict__ x,
               const int*   __restrict__ head,
               const float* __restrict__ kern,
               const float* __restrict__ bias,
               float*       __restrict__ out)
{
    extern __shared__ u32 smem[];
    u32* Wk = smem;                          // [128 k][64 w] fp16, chunk-swizzled
    u32* Xr = smem + WK_WORDS;               // raw fp32 X (cp.async landing)
    u32* XT = smem + WK_WORDS + XR_WORDS;    // [64 node][64 w] fp16, chunk-swizzled

    const int tid  = threadIdx.x;
    const int wid  = tid >> 5;               // 8 warps: 2m x 4n
    const int lane = tid & 31;
    const int gid  = lane >> 2;
    const int tig  = lane & 3;
    const int g    = blockIdx.x;
    const int h    = __ldg(head + g);

    const int m0 = (wid >> 2) * 32;          // 0, 32
    const int n0 = (wid & 3) * 32;           // 0, 32, 64, 96

    // ---- 1) X: raw fp32 cp.async (cold DRAM, latency hidden by W convert below) ----
    {
        const float* Xg = x + (size_t)g * NPG * IN_F;
        const u32 dstb = smem_addr(Xr);
        #pragma unroll
        for (int i = 0; i < 8; i++) {
            const int idx = tid + i * 256;   // 2048 x 16B
            CP_ASYNC16(dstb + (u32)idx * 16u, Xg + idx * 4);
        }
        CP_COMMIT();
    }

    // ---- 2) W: LDG (L2-hot) -> fp16 -> swizzled STS (overlaps X DRAM latency) ----
    {
        const float* W = kern + (size_t)h * IN_F * OUT_F;
        #pragma unroll
        for (int it = 0; it < 8; it++) {
            const int idx = tid + it * 256;        // 2048 chunks
            const int k   = idx >> 4;
            const int nc  = idx & 15;              // halfs 8nc..8nc+7
            const float4* src = (const float4*)(W + k * OUT_F + nc * 8);
            float4 v0 = src[0], v1 = src[1];
            uint4 o;
            o.x = pack_h2(v0.x, v0.y);
            o.y = pack_h2(v0.z, v0.w);
            o.z = pack_h2(v1.x, v1.y);
            o.w = pack_h2(v1.z, v1.w);
            *(uint4*)&Wk[k * 64 + ((nc ^ (k & 7)) << 2)] = o;
        }
    }

    // ---- 3) X: convert own cp.async chunks smem->smem (no barrier needed yet) ----
    CP_WAIT0();
    {
        #pragma unroll
        for (int i = 0; i < 8; i++) {
            const int idx  = tid + i * 256;        // same chunks this thread copied
            const int node = idx >> 5;
            const int c4   = idx & 31;             // 4 floats: k = 4*c4 .. 4*c4+3
            float4 v = *(const float4*)&Xr[idx * 4];
            const int kc = c4 >> 1;                // 16B k-chunk in XT
            u32* dst = &XT[node * 64 + ((kc ^ (node & 7)) << 2) + (c4 & 1) * 2];
            dst[0] = pack_h2(v.x, v.y);
            dst[1] = pack_h2(v.z, v.w);
        }
    }
    __syncthreads();

    float acc[2][4][4];
    #pragma unroll
    for (int i = 0; i < 2; i++)
        #pragma unroll
        for (int j = 0; j < 4; j++)
            #pragma unroll
            for (int r = 0; r < 4; r++)
                acc[i][j][r] = 0.0f;

    // A (non-trans LDSM): rows = m, chunks along k
    const int arow0 = m0 + (lane & 7) + 8 * ((lane >> 3) & 1);
    const int akc   = (lane >> 4) & 1;
    const u32 abase0 = smem_addr(&XT[arow0 * 64]);
    const u32 abase1 = smem_addr(&XT[(arow0 + 16) * 64]);
    const int ae0 = arow0 & 7, ae1 = (arow0 + 16) & 7;

    // B (trans LDSM): rows = k, chunks along n
    const int brow_off = (lane & 7) + 8 * ((lane >> 3) & 1);
    const int bnc_off  = (lane >> 4) & 1;

    #pragma unroll
    for (int s = 0; s < 8; s++) {
        u32 a0[4], a1[4];
        LDSM_X4(a0[0], a0[1], a0[2], a0[3], abase0 + ((((2 * s) + akc) ^ ae0) << 4));
        LDSM_X4(a1[0], a1[1], a1[2], a1[3], abase1 + ((((2 * s) + akc) ^ ae1) << 4));
        const int krow = 16 * s + brow_off;
        const u32 bstride = smem_addr(&Wk[krow * 64]);
        u32 b[2][4];
        #pragma unroll
        for (int p = 0; p < 2; p++) {
            const int nc = (n0 >> 3) + 2 * p + bnc_off;
            LDSM_X4_T(b[p][0], b[p][1], b[p][2], b[p][3],
                      bstride + ((nc ^ (krow & 7)) << 4));
        }
        #pragma unroll
        for (int j = 0; j < 4; j++) {
            const int p = j >> 1, q = j & 1;
            mma_f16(acc[0][j], a0[0], a0[1], a0[2], a0[3], b[p][2 * q], b[p][2 * q + 1]);
            mma_f16(acc[1][j], a1[0], a1[1], a1[2], a1[3], b[p][2 * q], b[p][2 * q + 1]);
        }
    }

    // ---- epilogue: bias + coalesced float2 stores ----
    float bb[4][2];
    #pragma unroll
    for (int j = 0; j < 4; j++) {
        const int col = n0 + 8 * j + 2 * tig;
        bb[j][0] = __ldg(bias + (size_t)h * OUT_F + col);
        bb[j][1] = __ldg(bias + (size_t)h * OUT_F + col + 1);
    }

    #pragma unroll
    for (int i = 0; i < 2; i++) {
        const int node0 = g * NPG + m0 + 16 * i + gid;
        #pragma unroll
        for (int j = 0; j < 4; j++) {
            const int col = n0 + 8 * j + 2 * tig;
            float2 v0 = make_float2(acc[i][j][0] + bb[j][0], acc[i][j][1] + bb[j][1]);
            float2 v1 = make_float2(acc[i][j][2] + bb[j][0], acc[i][j][3] + bb[j][1]);
            *(float2*)&out[(size_t)node0 * OUT_F + col]       = v0;
            *(float2*)&out[(size_t)(node0 + 8) * OUT_F + col] = v1;
        }
    }
}

extern "C" void kernel_launch(void* const* d_in, const int* in_sizes, int n_in,
                              void* d_out, int out_size)
{
    const float* inputs = (const float*)d_in[0];
    const int*   head   = (const int*)d_in[2];
    const float* kern   = (const float*)d_in[3];
    const float* bias   = (const float*)d_in[4];
    float*       out    = (float*)d_out;
    const int n_graphs  = in_sizes[2];   // 256

    static bool attr_set = false;
    if (!attr_set) {
        cudaFuncSetAttribute(mhl_mma_kernel, cudaFuncAttributeMaxDynamicSharedMemorySize, SMEM_BYTES);
        attr_set = true;
    }
    mhl_mma_kernel<<<n_graphs, 256, SMEM_BYTES>>>(inputs, head, kern, bias, out);
}